// round 1
// baseline (speedup 1.0000x reference)
#include <cuda_runtime.h>
#include <math.h>

#define NPTS 8192
#define HID 128
#define WARPS_PER_BLOCK 16
#define NBLOCKS 128
#define PTS_PER_WARP 4   // 128 blocks * 16 warps * 4 = 8192
#define WT_PITCH 132     // 128 + 4 pad -> conflict-free transposed rows

#define MU   80.77f
#define LAM  121.15f
#define GC   2.7e-3f
#define LEN  0.015f

// Per-warp partial sums (deterministic slots, no atomics)
__device__ double g_part[NBLOCKS * WARPS_PER_BLOCK][3];

// Shared memory layout (floats):
//   [0, 128*132)              W1T  (transposed, padded)
//   [128*132, 2*128*132)      W2T
//   [2*128*132, +16*7*128)    per-warp jet state
#define SMEM_FLOATS (2 * HID * WT_PITCH + WARPS_PER_BLOCK * 7 * HID)
#define SMEM_BYTES  (SMEM_FLOATS * 4)

__device__ __forceinline__ void hidden_layer(float* __restrict__ S,
                                             const float* __restrict__ WT,
                                             const float* __restrict__ b,
                                             int lane)
{
    float acc[4][7];
#pragma unroll
    for (int u = 0; u < 4; u++)
#pragma unroll
        for (int c = 0; c < 7; c++) acc[u][c] = 0.f;

#pragma unroll 2
    for (int i0 = 0; i0 < HID; i0 += 4) {
        float4 sv[7];
#pragma unroll
        for (int c = 0; c < 7; c++)
            sv[c] = *reinterpret_cast<const float4*>(S + c * HID + i0);
#pragma unroll
        for (int u = 0; u < 4; u++) {
            const float4 wv =
                *reinterpret_cast<const float4*>(WT + (lane + 32 * u) * WT_PITCH + i0);
#pragma unroll
            for (int c = 0; c < 7; c++) {
                acc[u][c] = fmaf(sv[c].x, wv.x, acc[u][c]);
                acc[u][c] = fmaf(sv[c].y, wv.y, acc[u][c]);
                acc[u][c] = fmaf(sv[c].z, wv.z, acc[u][c]);
                acc[u][c] = fmaf(sv[c].w, wv.w, acc[u][c]);
            }
        }
    }
    __syncwarp();   // everyone done READING S before we overwrite it
#pragma unroll
    for (int u = 0; u < 4; u++) {
        int j = lane + 32 * u;
        float zv = acc[u][0] + b[j];
        float T  = tanhf(zv);
        float Sx = 1.f - T * T;
        float c2 = -2.f * T * Sx;
        float z1 = acc[u][1], z2 = acc[u][2], zt = acc[u][3];
        S[0 * HID + j] = T;
        S[1 * HID + j] = Sx * z1;
        S[2 * HID + j] = Sx * z2;
        S[3 * HID + j] = Sx * zt;
        S[4 * HID + j] = fmaf(c2 * z1, z1, Sx * acc[u][4]);
        S[5 * HID + j] = fmaf(c2 * z1, z2, Sx * acc[u][5]);
        S[6 * HID + j] = fmaf(c2 * z2, z2, Sx * acc[u][6]);
    }
    __syncwarp();   // writes visible before next layer reads
}

__global__ __launch_bounds__(WARPS_PER_BLOCK * 32, 1)
void pinn_kernel(const float* __restrict__ x,  const float* __restrict__ t,
                 const float* __restrict__ W0, const float* __restrict__ b0,
                 const float* __restrict__ W1, const float* __restrict__ b1,
                 const float* __restrict__ W2, const float* __restrict__ b2,
                 const float* __restrict__ W3, const float* __restrict__ b3)
{
    extern __shared__ float smem[];
    float* W1T = smem;
    float* W2T = smem + HID * WT_PITCH;
    float* ST  = smem + 2 * HID * WT_PITCH;

    const int tid = threadIdx.x;
    // cooperative load + transpose of the two hidden weight matrices
    for (int idx = tid; idx < HID * HID; idx += WARPS_PER_BLOCK * 32) {
        int i = idx >> 7;      // input index (row of W)
        int j = idx & 127;     // output index (col of W)
        W1T[j * WT_PITCH + i] = W1[idx];
        W2T[j * WT_PITCH + i] = W2[idx];
    }
    __syncthreads();

    const int warp = tid >> 5;
    const int lane = tid & 31;
    float* S = ST + warp * 7 * HID;

    double a0 = 0.0, a1 = 0.0, a2 = 0.0;
    const int base = (blockIdx.x * WARPS_PER_BLOCK + warp) * PTS_PER_WARP;

    for (int k = 0; k < PTS_PER_WARP; k++) {
        const int p = base + k;
        const float x1 = x[2 * p], x2 = x[2 * p + 1], tt = t[p];

        // ---- layer 0 (3 -> 128) + tanh: jet seeded analytically ----
#pragma unroll
        for (int u = 0; u < 4; u++) {
            int j = lane + 32 * u;
            float w0 = W0[j], w1 = W0[HID + j], w2 = W0[2 * HID + j];
            float zv = fmaf(tt, w2, fmaf(x2, w1, fmaf(x1, w0, b0[j])));
            float T  = tanhf(zv);
            float Sx = 1.f - T * T;
            float c2 = -2.f * T * Sx;
            S[0 * HID + j] = T;
            S[1 * HID + j] = Sx * w0;       // d/dx1
            S[2 * HID + j] = Sx * w1;       // d/dx2
            S[3 * HID + j] = Sx * w2;       // d/dt
            S[4 * HID + j] = c2 * w0 * w0;  // d2/dx1dx1 (z'' = 0 in layer 0)
            S[5 * HID + j] = c2 * w0 * w1;  // d2/dx1dx2
            S[6 * HID + j] = c2 * w1 * w1;  // d2/dx2dx2
        }
        __syncwarp();

        hidden_layer(S, W1T, b1, lane);
        hidden_layer(S, W2T, b2, lane);

        // ---- final linear layer (128 -> 3), all 7 channels ----
        float o0[7], o1[7], o2[7];
#pragma unroll
        for (int c = 0; c < 7; c++) { o0[c] = 0.f; o1[c] = 0.f; o2[c] = 0.f; }
#pragma unroll
        for (int u = 0; u < 4; u++) {
            int j = lane + 32 * u;
            float wa = W3[3 * j], wb = W3[3 * j + 1], wc = W3[3 * j + 2];
#pragma unroll
            for (int c = 0; c < 7; c++) {
                float sv = S[c * HID + j];
                o0[c] = fmaf(sv, wa, o0[c]);
                o1[c] = fmaf(sv, wb, o1[c]);
                o2[c] = fmaf(sv, wc, o2[c]);
            }
        }
        __syncwarp();   // done reading S (next point's layer 0 will overwrite)

#pragma unroll
        for (int c = 0; c < 7; c++) {
#pragma unroll
            for (int off = 16; off; off >>= 1) {
                o0[c] += __shfl_down_sync(0xffffffffu, o0[c], off);
                o1[c] += __shfl_down_sync(0xffffffffu, o1[c], off);
                o2[c] += __shfl_down_sync(0xffffffffu, o2[c], off);
            }
        }

        if (lane == 0) {
            // channel map: 0=v 1=dx1 2=dx2 3=dt 4=dx1x1 5=dx1x2 6=dx2x2
            float s0   = o0[0] + b3[0];
            float phi  = expf(-s0);
            float s0_1 = o0[1], s0_2 = o0[2], s0_t = o0[3];
            float s0_11 = o0[4], s0_22 = o0[6];

            float u1_1 = o1[1], u1_2 = o1[2];
            float u2_1 = o2[1], u2_2 = o2[2];
            float u1_11 = o1[4], u1_12 = o1[5], u1_22 = o1[6];
            float u2_11 = o2[4], u2_12 = o2[5], u2_22 = o2[6];

            // div(sigma)
            float div1 = (MU + LAM) * (u1_11 + u2_12) + MU * (u1_11 + u1_22);
            float div2 = (MU + LAM) * (u1_12 + u2_22) + MU * (u2_11 + u2_22);
            float om   = 1.f - phi;
            float g    = om * om;
            float res_stress = fabsf(g * div1) + fabsf(g * div2);

            // psi
            float tr  = u1_1 + u2_2;
            float trp = 0.5f * (tr + fabsf(tr));
            float pos = 0.5f * (LAM + MU) * trp * trp;
            float e12 = 0.5f * (u1_2 + u2_1);
            float d11 = u1_1 - 0.5f * tr;
            float d22 = u2_2 - 0.5f * tr;
            float psi = pos + MU * (d11 * d11 + d22 * d22 + 2.f * e12 * e12);

            // phase-field residual
            float lap = phi * (s0_1 * s0_1 + s0_2 * s0_2 - s0_11 - s0_22);
            float pf  = GC * (phi / LEN - LEN * lap) - 2.f * om * psi;

            // irreversibility: relu(-dphi/dt), dphi/dt = -phi * s0_t
            float irr = fmaxf(phi * s0_t, 0.f);

            a0 += (double)(res_stress * res_stress);
            a1 += (double)(pf * pf);
            a2 += (double)irr;
        }
    }

    if (lane == 0) {
        const int wg = blockIdx.x * WARPS_PER_BLOCK + warp;
        g_part[wg][0] = a0;
        g_part[wg][1] = a1;
        g_part[wg][2] = a2;
    }
}

__global__ void reduce_kernel(float* __restrict__ out)
{
    const int warp = threadIdx.x >> 5;
    const int lane = threadIdx.x & 31;
    if (warp < 3) {
        double s = 0.0;
        for (int i = lane; i < NBLOCKS * WARPS_PER_BLOCK; i += 32)
            s += g_part[i][warp];
#pragma unroll
        for (int off = 16; off; off >>= 1)
            s += __shfl_down_sync(0xffffffffu, s, off);
        if (lane == 0) out[warp] = (float)(s / (double)NPTS);
    }
}

extern "C" void kernel_launch(void* const* d_in, const int* in_sizes, int n_in,
                              void* d_out, int out_size)
{
    const float* x  = (const float*)d_in[0];
    const float* t  = (const float*)d_in[1];
    const float* W0 = (const float*)d_in[2];
    const float* b0 = (const float*)d_in[3];
    const float* W1 = (const float*)d_in[4];
    const float* b1 = (const float*)d_in[5];
    const float* W2 = (const float*)d_in[6];
    const float* b2 = (const float*)d_in[7];
    const float* W3 = (const float*)d_in[8];
    const float* b3 = (const float*)d_in[9];

    cudaFuncSetAttribute(pinn_kernel,
                         cudaFuncAttributeMaxDynamicSharedMemorySize, SMEM_BYTES);

    pinn_kernel<<<NBLOCKS, WARPS_PER_BLOCK * 32, SMEM_BYTES>>>(
        x, t, W0, b0, W1, b1, W2, b2, W3, b3);
    reduce_kernel<<<1, 96>>>((float*)d_out);
}

// round 2
// speedup vs baseline: 1.0369x; 1.0369x over previous
#include <cuda_runtime.h>
#include <math.h>

#define NPTS 8192
#define HID 128
#define WARPS_PER_BLOCK 16
#define NTHREADS (WARPS_PER_BLOCK * 32)
#define NBLOCKS 128
#define PTS_PER_WARP 4   // 128 blocks * 16 warps * 4 = 8192
#define WT_PITCH 132     // 128 + 4 pad -> conflict-free transposed rows

#define MU   80.77f
#define LAM  121.15f
#define GC   2.7e-3f
#define LEN  0.015f

typedef unsigned long long u64;

// Per-warp partial sums (deterministic slots, no atomics on data)
__device__ double g_part[NBLOCKS * WARPS_PER_BLOCK][3];
__device__ int g_count = 0;   // self-resetting: returns to 0 after every launch

// Shared memory layout (floats):
//   [0, 128*132)              W1T  (transposed, padded)
//   [128*132, 2*128*132)      W2T
//   [2*128*132, +16*7*128)    per-warp jet state
#define SMEM_FLOATS (2 * HID * WT_PITCH + WARPS_PER_BLOCK * 7 * HID)
#define SMEM_BYTES  (SMEM_FLOATS * 4)

__device__ __forceinline__ u64 ffma2(u64 a, u64 b, u64 c)
{
    u64 d;
    asm("fma.rn.f32x2 %0, %1, %2, %3;" : "=l"(d) : "l"(a), "l"(b), "l"(c));
    return d;
}
__device__ __forceinline__ float pair_sum(u64 v)
{
    return __uint_as_float((unsigned)(v & 0xffffffffu)) +
           __uint_as_float((unsigned)(v >> 32));
}

__device__ __forceinline__ void hidden_layer(float* __restrict__ S,
                                             const float* __restrict__ WT,
                                             const float* __restrict__ b,
                                             int lane)
{
    // acc[u][c] is a packed float2: partial sums over even-i / odd-i
    u64 acc[4][7];
#pragma unroll
    for (int u = 0; u < 4; u++)
#pragma unroll
        for (int c = 0; c < 7; c++) acc[u][c] = 0ull;

#pragma unroll 2
    for (int i0 = 0; i0 < HID; i0 += 4) {
        ulonglong2 sv[7];   // (S[c][i0],S[c][i0+1]) , (S[c][i0+2],S[c][i0+3])
#pragma unroll
        for (int c = 0; c < 7; c++)
            sv[c] = *reinterpret_cast<const ulonglong2*>(S + c * HID + i0);
#pragma unroll
        for (int u = 0; u < 4; u++) {
            const ulonglong2 wv =
                *reinterpret_cast<const ulonglong2*>(WT + (lane + 32 * u) * WT_PITCH + i0);
#pragma unroll
            for (int c = 0; c < 7; c++) {
                acc[u][c] = ffma2(sv[c].x, wv.x, acc[u][c]);
                acc[u][c] = ffma2(sv[c].y, wv.y, acc[u][c]);
            }
        }
    }
    __syncwarp();   // everyone done READING S before we overwrite it
#pragma unroll
    for (int u = 0; u < 4; u++) {
        int j = lane + 32 * u;
        float af[7];
#pragma unroll
        for (int c = 0; c < 7; c++) af[c] = pair_sum(acc[u][c]);
        float zv = af[0] + b[j];
        float T  = tanhf(zv);
        float Sx = 1.f - T * T;
        float c2 = -2.f * T * Sx;
        float z1 = af[1], z2 = af[2], zt = af[3];
        S[0 * HID + j] = T;
        S[1 * HID + j] = Sx * z1;
        S[2 * HID + j] = Sx * z2;
        S[3 * HID + j] = Sx * zt;
        S[4 * HID + j] = fmaf(c2 * z1, z1, Sx * af[4]);
        S[5 * HID + j] = fmaf(c2 * z1, z2, Sx * af[5]);
        S[6 * HID + j] = fmaf(c2 * z2, z2, Sx * af[6]);
    }
    __syncwarp();   // writes visible before next layer reads
}

__global__ __launch_bounds__(NTHREADS, 1)
void pinn_kernel(const float* __restrict__ x,  const float* __restrict__ t,
                 const float* __restrict__ W0, const float* __restrict__ b0,
                 const float* __restrict__ W1, const float* __restrict__ b1,
                 const float* __restrict__ W2, const float* __restrict__ b2,
                 const float* __restrict__ W3, const float* __restrict__ b3,
                 float* __restrict__ out)
{
    extern __shared__ float smem[];
    float* W1T = smem;
    float* W2T = smem + HID * WT_PITCH;
    float* ST  = smem + 2 * HID * WT_PITCH;

    const int tid = threadIdx.x;
    // cooperative load + transpose of the two hidden weight matrices
    for (int idx = tid; idx < HID * HID; idx += NTHREADS) {
        int i = idx >> 7;      // input index (row of W)
        int j = idx & 127;     // output index (col of W)
        W1T[j * WT_PITCH + i] = W1[idx];
        W2T[j * WT_PITCH + i] = W2[idx];
    }
    __syncthreads();

    const int warp = tid >> 5;
    const int lane = tid & 31;
    float* S = ST + warp * 7 * HID;

    double a0 = 0.0, a1 = 0.0, a2 = 0.0;
    const int base = (blockIdx.x * WARPS_PER_BLOCK + warp) * PTS_PER_WARP;

    for (int k = 0; k < PTS_PER_WARP; k++) {
        const int p = base + k;
        const float x1 = x[2 * p], x2 = x[2 * p + 1], tt = t[p];

        // ---- layer 0 (3 -> 128) + tanh: jet seeded analytically ----
#pragma unroll
        for (int u = 0; u < 4; u++) {
            int j = lane + 32 * u;
            float w0 = W0[j], w1 = W0[HID + j], w2 = W0[2 * HID + j];
            float zv = fmaf(tt, w2, fmaf(x2, w1, fmaf(x1, w0, b0[j])));
            float T  = tanhf(zv);
            float Sx = 1.f - T * T;
            float c2 = -2.f * T * Sx;
            S[0 * HID + j] = T;
            S[1 * HID + j] = Sx * w0;       // d/dx1
            S[2 * HID + j] = Sx * w1;       // d/dx2
            S[3 * HID + j] = Sx * w2;       // d/dt
            S[4 * HID + j] = c2 * w0 * w0;  // d2/dx1dx1 (z'' = 0 in layer 0)
            S[5 * HID + j] = c2 * w0 * w1;  // d2/dx1dx2
            S[6 * HID + j] = c2 * w1 * w1;  // d2/dx2dx2
        }
        __syncwarp();

        hidden_layer(S, W1T, b1, lane);
        hidden_layer(S, W2T, b2, lane);

        // ---- final linear layer (128 -> 3), all 7 channels ----
        float o0[7], o1[7], o2[7];
#pragma unroll
        for (int c = 0; c < 7; c++) { o0[c] = 0.f; o1[c] = 0.f; o2[c] = 0.f; }
#pragma unroll
        for (int u = 0; u < 4; u++) {
            int j = lane + 32 * u;
            float wa = W3[3 * j], wb = W3[3 * j + 1], wc = W3[3 * j + 2];
#pragma unroll
            for (int c = 0; c < 7; c++) {
                float sv = S[c * HID + j];
                o0[c] = fmaf(sv, wa, o0[c]);
                o1[c] = fmaf(sv, wb, o1[c]);
                o2[c] = fmaf(sv, wc, o2[c]);
            }
        }
        __syncwarp();   // done reading S (next point's layer 0 will overwrite)

#pragma unroll
        for (int c = 0; c < 7; c++) {
#pragma unroll
            for (int off = 16; off; off >>= 1) {
                o0[c] += __shfl_down_sync(0xffffffffu, o0[c], off);
                o1[c] += __shfl_down_sync(0xffffffffu, o1[c], off);
                o2[c] += __shfl_down_sync(0xffffffffu, o2[c], off);
            }
        }

        if (lane == 0) {
            // channel map: 0=v 1=dx1 2=dx2 3=dt 4=dx1x1 5=dx1x2 6=dx2x2
            float s0   = o0[0] + b3[0];
            float phi  = expf(-s0);
            float s0_1 = o0[1], s0_2 = o0[2], s0_t = o0[3];
            float s0_11 = o0[4], s0_22 = o0[6];

            float u1_1 = o1[1], u1_2 = o1[2];
            float u2_1 = o2[1], u2_2 = o2[2];
            float u1_11 = o1[4], u1_12 = o1[5], u1_22 = o1[6];
            float u2_11 = o2[4], u2_12 = o2[5], u2_22 = o2[6];

            // div(sigma)
            float div1 = (MU + LAM) * (u1_11 + u2_12) + MU * (u1_11 + u1_22);
            float div2 = (MU + LAM) * (u1_12 + u2_22) + MU * (u2_11 + u2_22);
            float om   = 1.f - phi;
            float g    = om * om;
            float res_stress = fabsf(g * div1) + fabsf(g * div2);

            // psi
            float tr  = u1_1 + u2_2;
            float trp = 0.5f * (tr + fabsf(tr));
            float pos = 0.5f * (LAM + MU) * trp * trp;
            float e12 = 0.5f * (u1_2 + u2_1);
            float d11 = u1_1 - 0.5f * tr;
            float d22 = u2_2 - 0.5f * tr;
            float psi = pos + MU * (d11 * d11 + d22 * d22 + 2.f * e12 * e12);

            // phase-field residual
            float lap = phi * (s0_1 * s0_1 + s0_2 * s0_2 - s0_11 - s0_22);
            float pf  = GC * (phi / LEN - LEN * lap) - 2.f * om * psi;

            // irreversibility: relu(-dphi/dt), dphi/dt = -phi * s0_t
            float irr = fmaxf(phi * s0_t, 0.f);

            a0 += (double)(res_stress * res_stress);
            a1 += (double)(pf * pf);
            a2 += (double)irr;
        }
    }

    if (lane == 0) {
        const int wg = blockIdx.x * WARPS_PER_BLOCK + warp;
        g_part[wg][0] = a0;
        g_part[wg][1] = a1;
        g_part[wg][2] = a2;
    }

    // ---- fused deterministic final reduction (last block done) ----
    __shared__ int is_last;
    __shared__ double red[WARPS_PER_BLOCK][3];
    __syncthreads();
    if (tid == 0) {
        __threadfence();
        int v = atomicAdd(&g_count, 1);
        is_last = (v == NBLOCKS - 1) ? 1 : 0;
    }
    __syncthreads();
    if (is_last) {
        __threadfence();   // acquire: make other blocks' partials visible
        double s[3] = {0.0, 0.0, 0.0};
#pragma unroll
        for (int r = 0; r < (NBLOCKS * WARPS_PER_BLOCK) / NTHREADS; r++) {
            int i = tid + r * NTHREADS;
            s[0] += g_part[i][0];
            s[1] += g_part[i][1];
            s[2] += g_part[i][2];
        }
#pragma unroll
        for (int c = 0; c < 3; c++)
#pragma unroll
            for (int off = 16; off; off >>= 1)
                s[c] += __shfl_down_sync(0xffffffffu, s[c], off);
        if (lane == 0) {
            red[warp][0] = s[0]; red[warp][1] = s[1]; red[warp][2] = s[2];
        }
        __syncthreads();
        if (warp == 0) {
            double v0 = (lane < WARPS_PER_BLOCK) ? red[lane][0] : 0.0;
            double v1 = (lane < WARPS_PER_BLOCK) ? red[lane][1] : 0.0;
            double v2 = (lane < WARPS_PER_BLOCK) ? red[lane][2] : 0.0;
#pragma unroll
            for (int off = 8; off; off >>= 1) {
                v0 += __shfl_down_sync(0xffffffffu, v0, off);
                v1 += __shfl_down_sync(0xffffffffu, v1, off);
                v2 += __shfl_down_sync(0xffffffffu, v2, off);
            }
            if (lane == 0) {
                out[0] = (float)(v0 / (double)NPTS);
                out[1] = (float)(v1 / (double)NPTS);
                out[2] = (float)(v2 / (double)NPTS);
                g_count = 0;   // reset for next (graph-replayed) launch
            }
        }
    }
}

extern "C" void kernel_launch(void* const* d_in, const int* in_sizes, int n_in,
                              void* d_out, int out_size)
{
    const float* x  = (const float*)d_in[0];
    const float* t  = (const float*)d_in[1];
    const float* W0 = (const float*)d_in[2];
    const float* b0 = (const float*)d_in[3];
    const float* W1 = (const float*)d_in[4];
    const float* b1 = (const float*)d_in[5];
    const float* W2 = (const float*)d_in[6];
    const float* b2 = (const float*)d_in[7];
    const float* W3 = (const float*)d_in[8];
    const float* b3 = (const float*)d_in[9];

    cudaFuncSetAttribute(pinn_kernel,
                         cudaFuncAttributeMaxDynamicSharedMemorySize, SMEM_BYTES);

    pinn_kernel<<<NBLOCKS, NTHREADS, SMEM_BYTES>>>(
        x, t, W0, b0, W1, b1, W2, b2, W3, b3, (float*)d_out);
}

// round 3
// speedup vs baseline: 1.0961x; 1.0571x over previous
#include <cuda_runtime.h>
#include <math.h>

#define NPTS 8192
#define HID 128
#define WARPS_PER_BLOCK 16
#define NTHREADS (WARPS_PER_BLOCK * 32)
#define NBLOCKS 148
#define NWG (NBLOCKS * WARPS_PER_BLOCK)
#define WT_PITCH 132     // 128 + 4 pad -> conflict-free strided LDS.128

#define MU   80.77f
#define LAM  121.15f
#define GC   2.7e-3f
#define LEN  0.015f

typedef unsigned long long u64;

// Per-warp partial sums (deterministic slots, no atomics on data)
__device__ double g_part[NWG][3];
__device__ int g_count = 0;   // self-resetting: returns to 0 after every launch

// Shared memory layout (floats):
//   [0, 128*132)              W1T  (transposed, padded)
//   [128*132, 2*128*132)      W2T
//   [2*128*132, +16*7*128)    per-warp jet state
#define SMEM_FLOATS (2 * HID * WT_PITCH + WARPS_PER_BLOCK * 7 * HID)
#define SMEM_BYTES  (SMEM_FLOATS * 4)

__device__ __forceinline__ u64 ffma2(u64 a, u64 b, u64 c)
{
    u64 d;
    asm("fma.rn.f32x2 %0, %1, %2, %3;" : "=l"(d) : "l"(a), "l"(b), "l"(c));
    return d;
}
__device__ __forceinline__ float pair_sum(u64 v)
{
    return __uint_as_float((unsigned)(v & 0xffffffffu)) +
           __uint_as_float((unsigned)(v >> 32));
}

// activation jet update for one output unit j, given pre-activation jet af[7]
__device__ __forceinline__ void write_act(float* __restrict__ S,
                                          const float* __restrict__ af,
                                          float bj, int j)
{
    float zv = af[0] + bj;
    float T  = tanhf(zv);
    float Sx = 1.f - T * T;
    float c2 = -2.f * T * Sx;
    float z1 = af[1], z2 = af[2], zt = af[3];
    S[0 * HID + j] = T;
    S[1 * HID + j] = Sx * z1;
    S[2 * HID + j] = Sx * z2;
    S[3 * HID + j] = Sx * zt;
    S[4 * HID + j] = fmaf(c2 * z1, z1, Sx * af[4]);
    S[5 * HID + j] = fmaf(c2 * z1, z2, Sx * af[5]);
    S[6 * HID + j] = fmaf(c2 * z2, z2, Sx * af[6]);
}

__device__ __forceinline__ void hidden_layer(float* __restrict__ S,
                                             const float* __restrict__ WT,
                                             const float* __restrict__ b,
                                             int lane)
{
    float stash[14];       // pass-A pre-activation jets (j = lane, lane+32)
    float af2[14];         // pass-B pre-activation jets (j = lane+64, lane+96)

#pragma unroll
    for (int half = 0; half < 2; half++) {
        u64 acc[2][7];
#pragma unroll
        for (int u = 0; u < 2; u++)
#pragma unroll
            for (int c = 0; c < 7; c++) acc[u][c] = 0ull;

#pragma unroll 2
        for (int i0 = 0; i0 < HID; i0 += 4) {
            ulonglong2 sv[7];   // broadcast: (S[c][i0..i0+1]),(S[c][i0+2..i0+3])
#pragma unroll
            for (int c = 0; c < 7; c++)
                sv[c] = *reinterpret_cast<const ulonglong2*>(S + c * HID + i0);
#pragma unroll
            for (int u = 0; u < 2; u++) {
                const int j = lane + 32 * (2 * half + u);
                const ulonglong2 wv =
                    *reinterpret_cast<const ulonglong2*>(WT + j * WT_PITCH + i0);
#pragma unroll
                for (int c = 0; c < 7; c++) {
                    acc[u][c] = ffma2(sv[c].x, wv.x, acc[u][c]);
                    acc[u][c] = ffma2(sv[c].y, wv.y, acc[u][c]);
                }
            }
        }
        float* dst = (half == 0) ? stash : af2;
#pragma unroll
        for (int u = 0; u < 2; u++)
#pragma unroll
            for (int c = 0; c < 7; c++)
                dst[u * 7 + c] = pair_sum(acc[u][c]);
    }

    __syncwarp();   // everyone done READING S before we overwrite it
    write_act(S, stash,     b[lane],      lane);
    write_act(S, stash + 7, b[lane + 32], lane + 32);
    write_act(S, af2,       b[lane + 64], lane + 64);
    write_act(S, af2 + 7,   b[lane + 96], lane + 96);
    __syncwarp();   // writes visible before next layer reads
}

__global__ __launch_bounds__(NTHREADS, 1)
void pinn_kernel(const float* __restrict__ x,  const float* __restrict__ t,
                 const float* __restrict__ W0, const float* __restrict__ b0,
                 const float* __restrict__ W1, const float* __restrict__ b1,
                 const float* __restrict__ W2, const float* __restrict__ b2,
                 const float* __restrict__ W3, const float* __restrict__ b3,
                 float* __restrict__ out)
{
    extern __shared__ float smem[];
    float* W1T = smem;
    float* W2T = smem + HID * WT_PITCH;
    float* ST  = smem + 2 * HID * WT_PITCH;

    const int tid = threadIdx.x;
    // cooperative load + transpose of the two hidden weight matrices
    for (int idx = tid; idx < HID * HID; idx += NTHREADS) {
        int i = idx >> 7;      // input index (row of W)
        int j = idx & 127;     // output index (col of W)
        W1T[j * WT_PITCH + i] = W1[idx];
        W2T[j * WT_PITCH + i] = W2[idx];
    }
    __syncthreads();

    const int warp = tid >> 5;
    const int lane = tid & 31;
    float* S = ST + warp * 7 * HID;

    double a0 = 0.0, a1 = 0.0, a2 = 0.0;

    // balanced point range for this block; warp-strided within block
    const int pstart = (blockIdx.x * NPTS) / NBLOCKS;
    const int pend   = ((blockIdx.x + 1) * NPTS) / NBLOCKS;

    for (int p = pstart + warp; p < pend; p += WARPS_PER_BLOCK) {
        const float x1 = x[2 * p], x2 = x[2 * p + 1], tt = t[p];

        // ---- layer 0 (3 -> 128) + tanh: jet seeded analytically ----
#pragma unroll
        for (int u = 0; u < 4; u++) {
            int j = lane + 32 * u;
            float w0 = W0[j], w1 = W0[HID + j], w2 = W0[2 * HID + j];
            float zv = fmaf(tt, w2, fmaf(x2, w1, fmaf(x1, w0, b0[j])));
            float T  = tanhf(zv);
            float Sx = 1.f - T * T;
            float c2 = -2.f * T * Sx;
            S[0 * HID + j] = T;
            S[1 * HID + j] = Sx * w0;       // d/dx1
            S[2 * HID + j] = Sx * w1;       // d/dx2
            S[3 * HID + j] = Sx * w2;       // d/dt
            S[4 * HID + j] = c2 * w0 * w0;  // d2/dx1dx1 (z'' = 0 in layer 0)
            S[5 * HID + j] = c2 * w0 * w1;  // d2/dx1dx2
            S[6 * HID + j] = c2 * w1 * w1;  // d2/dx2dx2
        }
        __syncwarp();

        hidden_layer(S, W1T, b1, lane);
        hidden_layer(S, W2T, b2, lane);

        // ---- final linear layer (128 -> 3), all 7 channels ----
        float o0[7], o1[7], o2[7];
#pragma unroll
        for (int c = 0; c < 7; c++) { o0[c] = 0.f; o1[c] = 0.f; o2[c] = 0.f; }
#pragma unroll
        for (int u = 0; u < 4; u++) {
            int j = lane + 32 * u;
            float wa = W3[3 * j], wb = W3[3 * j + 1], wc = W3[3 * j + 2];
#pragma unroll
            for (int c = 0; c < 7; c++) {
                float sv = S[c * HID + j];
                o0[c] = fmaf(sv, wa, o0[c]);
                o1[c] = fmaf(sv, wb, o1[c]);
                o2[c] = fmaf(sv, wc, o2[c]);
            }
        }
        __syncwarp();   // done reading S (next point's layer 0 will overwrite)

#pragma unroll
        for (int c = 0; c < 7; c++) {
#pragma unroll
            for (int off = 16; off; off >>= 1) {
                o0[c] += __shfl_down_sync(0xffffffffu, o0[c], off);
                o1[c] += __shfl_down_sync(0xffffffffu, o1[c], off);
                o2[c] += __shfl_down_sync(0xffffffffu, o2[c], off);
            }
        }

        if (lane == 0) {
            // channel map: 0=v 1=dx1 2=dx2 3=dt 4=dx1x1 5=dx1x2 6=dx2x2
            float s0   = o0[0] + b3[0];
            float phi  = expf(-s0);
            float s0_1 = o0[1], s0_2 = o0[2], s0_t = o0[3];
            float s0_11 = o0[4], s0_22 = o0[6];

            float u1_1 = o1[1], u1_2 = o1[2];
            float u2_1 = o2[1], u2_2 = o2[2];
            float u1_11 = o1[4], u1_12 = o1[5], u1_22 = o1[6];
            float u2_11 = o2[4], u2_12 = o2[5], u2_22 = o2[6];

            // div(sigma)
            float div1 = (MU + LAM) * (u1_11 + u2_12) + MU * (u1_11 + u1_22);
            float div2 = (MU + LAM) * (u1_12 + u2_22) + MU * (u2_11 + u2_22);
            float om   = 1.f - phi;
            float g    = om * om;
            float res_stress = fabsf(g * div1) + fabsf(g * div2);

            // psi
            float tr  = u1_1 + u2_2;
            float trp = 0.5f * (tr + fabsf(tr));
            float pos = 0.5f * (LAM + MU) * trp * trp;
            float e12 = 0.5f * (u1_2 + u2_1);
            float d11 = u1_1 - 0.5f * tr;
            float d22 = u2_2 - 0.5f * tr;
            float psi = pos + MU * (d11 * d11 + d22 * d22 + 2.f * e12 * e12);

            // phase-field residual
            float lap = phi * (s0_1 * s0_1 + s0_2 * s0_2 - s0_11 - s0_22);
            float pf  = GC * (phi / LEN - LEN * lap) - 2.f * om * psi;

            // irreversibility: relu(-dphi/dt), dphi/dt = -phi * s0_t
            float irr = fmaxf(phi * s0_t, 0.f);

            a0 += (double)(res_stress * res_stress);
            a1 += (double)(pf * pf);
            a2 += (double)irr;
        }
    }

    if (lane == 0) {
        const int wg = blockIdx.x * WARPS_PER_BLOCK + warp;
        g_part[wg][0] = a0;
        g_part[wg][1] = a1;
        g_part[wg][2] = a2;
    }

    // ---- fused deterministic final reduction (last block done) ----
    __shared__ int is_last;
    __shared__ double red[WARPS_PER_BLOCK][3];
    __syncthreads();
    if (tid == 0) {
        __threadfence();
        int v = atomicAdd(&g_count, 1);
        is_last = (v == NBLOCKS - 1) ? 1 : 0;
    }
    __syncthreads();
    if (is_last) {
        __threadfence();   // acquire: make other blocks' partials visible
        double s[3] = {0.0, 0.0, 0.0};
        for (int i = tid; i < NWG; i += NTHREADS) {
            s[0] += g_part[i][0];
            s[1] += g_part[i][1];
            s[2] += g_part[i][2];
        }
#pragma unroll
        for (int c = 0; c < 3; c++)
#pragma unroll
            for (int off = 16; off; off >>= 1)
                s[c] += __shfl_down_sync(0xffffffffu, s[c], off);
        if (lane == 0) {
            red[warp][0] = s[0]; red[warp][1] = s[1]; red[warp][2] = s[2];
        }
        __syncthreads();
        if (warp == 0) {
            double v0 = (lane < WARPS_PER_BLOCK) ? red[lane][0] : 0.0;
            double v1 = (lane < WARPS_PER_BLOCK) ? red[lane][1] : 0.0;
            double v2 = (lane < WARPS_PER_BLOCK) ? red[lane][2] : 0.0;
#pragma unroll
            for (int off = 8; off; off >>= 1) {
                v0 += __shfl_down_sync(0xffffffffu, v0, off);
                v1 += __shfl_down_sync(0xffffffffu, v1, off);
                v2 += __shfl_down_sync(0xffffffffu, v2, off);
            }
            if (lane == 0) {
                out[0] = (float)(v0 / (double)NPTS);
                out[1] = (float)(v1 / (double)NPTS);
                out[2] = (float)(v2 / (double)NPTS);
                g_count = 0;   // reset for next (graph-replayed) launch
            }
        }
    }
}

extern "C" void kernel_launch(void* const* d_in, const int* in_sizes, int n_in,
                              void* d_out, int out_size)
{
    const float* x  = (const float*)d_in[0];
    const float* t  = (const float*)d_in[1];
    const float* W0 = (const float*)d_in[2];
    const float* b0 = (const float*)d_in[3];
    const float* W1 = (const float*)d_in[4];
    const float* b1 = (const float*)d_in[5];
    const float* W2 = (const float*)d_in[6];
    const float* b2 = (const float*)d_in[7];
    const float* W3 = (const float*)d_in[8];
    const float* b3 = (const float*)d_in[9];

    cudaFuncSetAttribute(pinn_kernel,
                         cudaFuncAttributeMaxDynamicSharedMemorySize, SMEM_BYTES);

    pinn_kernel<<<NBLOCKS, NTHREADS, SMEM_BYTES>>>(
        x, t, W0, b0, W1, b1, W2, b2, W3, b3, (float*)d_out);
}

// round 5
// speedup vs baseline: 1.1885x; 1.0843x over previous
#include <cuda_runtime.h>
#include <math.h>

#define NPTS 8192
#define HID 128
#define WARPS_PER_BLOCK 16
#define NTHREADS (WARPS_PER_BLOCK * 32)
#define NBLOCKS 148
#define NWG (NBLOCKS * WARPS_PER_BLOCK)
#define WT_PITCH 132     // 128 + 4 pad -> conflict-free strided LDS.128

#define MU   80.77f
#define LAM  121.15f
#define GC   2.7e-3f
#define LEN  0.015f

typedef unsigned long long u64;

// Per-warp partial sums (deterministic slots, no atomics on data)
__device__ double g_part[NWG][3];
__device__ int g_count = 0;   // self-resetting: returns to 0 after every launch

// Shared memory layout (floats):
//   [0, 128*132)              W1T  (transposed, padded)
//   [128*132, 2*128*132)      W2T
//   [2*128*132, +16*7*128)    per-warp jet state
#define SMEM_FLOATS (2 * HID * WT_PITCH + WARPS_PER_BLOCK * 7 * HID)
#define SMEM_BYTES  (SMEM_FLOATS * 4)

__device__ __forceinline__ u64 ffma2(u64 a, u64 b, u64 c)
{
    u64 d;
    asm("fma.rn.f32x2 %0, %1, %2, %3;" : "=l"(d) : "l"(a), "l"(b), "l"(c));
    return d;
}
__device__ __forceinline__ float pair_sum(u64 v)
{
    return __uint_as_float((unsigned)(v & 0xffffffffu)) +
           __uint_as_float((unsigned)(v >> 32));
}

// activation jet update for one output unit j, given pre-activation jet af[7]
__device__ __forceinline__ void write_act(float* __restrict__ S,
                                          const float* __restrict__ af,
                                          float bj, int j)
{
    float zv = af[0] + bj;
    float T  = tanhf(zv);
    float Sx = 1.f - T * T;
    float c2 = -2.f * T * Sx;
    float z1 = af[1], z2 = af[2], zt = af[3];
    S[0 * HID + j] = T;
    S[1 * HID + j] = Sx * z1;
    S[2 * HID + j] = Sx * z2;
    S[3 * HID + j] = Sx * zt;
    S[4 * HID + j] = fmaf(c2 * z1, z1, Sx * af[4]);
    S[5 * HID + j] = fmaf(c2 * z1, z2, Sx * af[5]);
    S[6 * HID + j] = fmaf(c2 * z2, z2, Sx * af[6]);
}

__device__ __forceinline__ void hidden_layer(float* __restrict__ S,
                                             const float* __restrict__ WT,
                                             const float* __restrict__ b,
                                             int lane)
{
    // acc[u][c]: packed float2 partial sums (even-i / odd-i lanes of K)
    u64 acc[4][7];
#pragma unroll
    for (int u = 0; u < 4; u++)
#pragma unroll
        for (int c = 0; c < 7; c++) acc[u][c] = 0ull;

    const float* w0p = WT + lane * WT_PITCH;

    for (int i0 = 0; i0 < HID; i0 += 4) {
        // 4 strided weight vectors (one per output unit), read ONCE per chunk
        ulonglong2 wv[4];
#pragma unroll
        for (int u = 0; u < 4; u++)
            wv[u] = *reinterpret_cast<const ulonglong2*>(w0p + u * (32 * WT_PITCH) + i0);
        // channel-inner: one broadcast jet read, 8 packed FMAs
#pragma unroll
        for (int c = 0; c < 7; c++) {
            const ulonglong2 sv = *reinterpret_cast<const ulonglong2*>(S + c * HID + i0);
            acc[0][c] = ffma2(sv.x, wv[0].x, acc[0][c]);
            acc[0][c] = ffma2(sv.y, wv[0].y, acc[0][c]);
            acc[1][c] = ffma2(sv.x, wv[1].x, acc[1][c]);
            acc[1][c] = ffma2(sv.y, wv[1].y, acc[1][c]);
            acc[2][c] = ffma2(sv.x, wv[2].x, acc[2][c]);
            acc[2][c] = ffma2(sv.y, wv[2].y, acc[2][c]);
            acc[3][c] = ffma2(sv.x, wv[3].x, acc[3][c]);
            acc[3][c] = ffma2(sv.y, wv[3].y, acc[3][c]);
        }
    }

    __syncwarp();   // everyone done READING S before we overwrite it
#pragma unroll
    for (int u = 0; u < 4; u++) {
        int j = lane + 32 * u;
        float af[7];
#pragma unroll
        for (int c = 0; c < 7; c++) af[c] = pair_sum(acc[u][c]);
        write_act(S, af, b[j], j);
    }
    __syncwarp();   // writes visible before next layer reads
}

__global__ __launch_bounds__(NTHREADS, 1)
void pinn_kernel(const float* __restrict__ x,  const float* __restrict__ t,
                 const float* __restrict__ W0, const float* __restrict__ b0,
                 const float* __restrict__ W1, const float* __restrict__ b1,
                 const float* __restrict__ W2, const float* __restrict__ b2,
                 const float* __restrict__ W3, const float* __restrict__ b3,
                 float* __restrict__ out)
{
    extern __shared__ float smem[];
    float* W1T = smem;
    float* W2T = smem + HID * WT_PITCH;
    float* ST  = smem + 2 * HID * WT_PITCH;

    const int tid = threadIdx.x;
    // cooperative load + transpose of the two hidden weight matrices
    for (int idx = tid; idx < HID * HID; idx += NTHREADS) {
        int i = idx >> 7;      // input index (row of W)
        int j = idx & 127;     // output index (col of W)
        W1T[j * WT_PITCH + i] = W1[idx];
        W2T[j * WT_PITCH + i] = W2[idx];
    }
    __syncthreads();

    const int warp = tid >> 5;
    const int lane = tid & 31;
    float* S = ST + warp * 7 * HID;

    double a0 = 0.0, a1 = 0.0, a2 = 0.0;

    // balanced point range for this block; warp-strided within block
    const int pstart = (blockIdx.x * NPTS) / NBLOCKS;
    const int pend   = ((blockIdx.x + 1) * NPTS) / NBLOCKS;

    for (int p = pstart + warp; p < pend; p += WARPS_PER_BLOCK) {
        const float x1 = x[2 * p], x2 = x[2 * p + 1], tt = t[p];

        // ---- layer 0 (3 -> 128) + tanh: jet seeded analytically ----
#pragma unroll
        for (int u = 0; u < 4; u++) {
            int j = lane + 32 * u;
            float w0 = W0[j], w1 = W0[HID + j], w2 = W0[2 * HID + j];
            float zv = fmaf(tt, w2, fmaf(x2, w1, fmaf(x1, w0, b0[j])));
            float T  = tanhf(zv);
            float Sx = 1.f - T * T;
            float c2 = -2.f * T * Sx;
            S[0 * HID + j] = T;
            S[1 * HID + j] = Sx * w0;       // d/dx1
            S[2 * HID + j] = Sx * w1;       // d/dx2
            S[3 * HID + j] = Sx * w2;       // d/dt
            S[4 * HID + j] = c2 * w0 * w0;  // d2/dx1dx1 (z'' = 0 in layer 0)
            S[5 * HID + j] = c2 * w0 * w1;  // d2/dx1dx2
            S[6 * HID + j] = c2 * w1 * w1;  // d2/dx2dx2
        }
        __syncwarp();

        hidden_layer(S, W1T, b1, lane);
        hidden_layer(S, W2T, b2, lane);

        // ---- final linear layer (128 -> 3), all 7 channels ----
        float o0[7], o1[7], o2[7];
#pragma unroll
        for (int c = 0; c < 7; c++) { o0[c] = 0.f; o1[c] = 0.f; o2[c] = 0.f; }
#pragma unroll
        for (int u = 0; u < 4; u++) {
            int j = lane + 32 * u;
            float wa = W3[3 * j], wb = W3[3 * j + 1], wc = W3[3 * j + 2];
#pragma unroll
            for (int c = 0; c < 7; c++) {
                float sv = S[c * HID + j];
                o0[c] = fmaf(sv, wa, o0[c]);
                o1[c] = fmaf(sv, wb, o1[c]);
                o2[c] = fmaf(sv, wc, o2[c]);
            }
        }
        __syncwarp();   // done reading S (next point's layer 0 will overwrite)

#pragma unroll
        for (int c = 0; c < 7; c++) {
#pragma unroll
            for (int off = 16; off; off >>= 1) {
                o0[c] += __shfl_down_sync(0xffffffffu, o0[c], off);
                o1[c] += __shfl_down_sync(0xffffffffu, o1[c], off);
                o2[c] += __shfl_down_sync(0xffffffffu, o2[c], off);
            }
        }

        if (lane == 0) {
            // channel map: 0=v 1=dx1 2=dx2 3=dt 4=dx1x1 5=dx1x2 6=dx2x2
            float s0   = o0[0] + b3[0];
            float phi  = expf(-s0);
            float s0_1 = o0[1], s0_2 = o0[2], s0_t = o0[3];
            float s0_11 = o0[4], s0_22 = o0[6];

            float u1_1 = o1[1], u1_2 = o1[2];
            float u2_1 = o2[1], u2_2 = o2[2];
            float u1_11 = o1[4], u1_12 = o1[5], u1_22 = o1[6];
            float u2_11 = o2[4], u2_12 = o2[5], u2_22 = o2[6];

            // div(sigma)
            float div1 = (MU + LAM) * (u1_11 + u2_12) + MU * (u1_11 + u1_22);
            float div2 = (MU + LAM) * (u1_12 + u2_22) + MU * (u2_11 + u2_22);
            float om   = 1.f - phi;
            float g    = om * om;
            float res_stress = fabsf(g * div1) + fabsf(g * div2);

            // psi
            float tr  = u1_1 + u2_2;
            float trp = 0.5f * (tr + fabsf(tr));
            float pos = 0.5f * (LAM + MU) * trp * trp;
            float e12 = 0.5f * (u1_2 + u2_1);
            float d11 = u1_1 - 0.5f * tr;
            float d22 = u2_2 - 0.5f * tr;
            float psi = pos + MU * (d11 * d11 + d22 * d22 + 2.f * e12 * e12);

            // phase-field residual
            float lap = phi * (s0_1 * s0_1 + s0_2 * s0_2 - s0_11 - s0_22);
            float pf  = GC * (phi / LEN - LEN * lap) - 2.f * om * psi;

            // irreversibility: relu(-dphi/dt), dphi/dt = -phi * s0_t
            float irr = fmaxf(phi * s0_t, 0.f);

            a0 += (double)(res_stress * res_stress);
            a1 += (double)(pf * pf);
            a2 += (double)irr;
        }
    }

    if (lane == 0) {
        const int wg = blockIdx.x * WARPS_PER_BLOCK + warp;
        g_part[wg][0] = a0;
        g_part[wg][1] = a1;
        g_part[wg][2] = a2;
    }

    // ---- fused deterministic final reduction (last block done) ----
    __shared__ int is_last;
    __shared__ double red[WARPS_PER_BLOCK][3];
    __syncthreads();
    if (tid == 0) {
        __threadfence();
        int v = atomicAdd(&g_count, 1);
        is_last = (v == NBLOCKS - 1) ? 1 : 0;
    }
    __syncthreads();
    if (is_last) {
        __threadfence();   // acquire: make other blocks' partials visible
        double s[3] = {0.0, 0.0, 0.0};
        for (int i = tid; i < NWG; i += NTHREADS) {
            s[0] += g_part[i][0];
            s[1] += g_part[i][1];
            s[2] += g_part[i][2];
        }
#pragma unroll
        for (int c = 0; c < 3; c++)
#pragma unroll
            for (int off = 16; off; off >>= 1)
                s[c] += __shfl_down_sync(0xffffffffu, s[c], off);
        if (lane == 0) {
            red[warp][0] = s[0]; red[warp][1] = s[1]; red[warp][2] = s[2];
        }
        __syncthreads();
        if (warp == 0) {
            double v0 = (lane < WARPS_PER_BLOCK) ? red[lane][0] : 0.0;
            double v1 = (lane < WARPS_PER_BLOCK) ? red[lane][1] : 0.0;
            double v2 = (lane < WARPS_PER_BLOCK) ? red[lane][2] : 0.0;
#pragma unroll
            for (int off = 8; off; off >>= 1) {
                v0 += __shfl_down_sync(0xffffffffu, v0, off);
                v1 += __shfl_down_sync(0xffffffffu, v1, off);
                v2 += __shfl_down_sync(0xffffffffu, v2, off);
            }
            if (lane == 0) {
                out[0] = (float)(v0 / (double)NPTS);
                out[1] = (float)(v1 / (double)NPTS);
                out[2] = (float)(v2 / (double)NPTS);
                g_count = 0;   // reset for next (graph-replayed) launch
            }
        }
    }
}

extern "C" void kernel_launch(void* const* d_in, const int* in_sizes, int n_in,
                              void* d_out, int out_size)
{
    const float* x  = (const float*)d_in[0];
    const float* t  = (const float*)d_in[1];
    const float* W0 = (const float*)d_in[2];
    const float* b0 = (const float*)d_in[3];
    const float* W1 = (const float*)d_in[4];
    const float* b1 = (const float*)d_in[5];
    const float* W2 = (const float*)d_in[6];
    const float* b2 = (const float*)d_in[7];
    const float* W3 = (const float*)d_in[8];
    const float* b3 = (const float*)d_in[9];

    cudaFuncSetAttribute(pinn_kernel,
                         cudaFuncAttributeMaxDynamicSharedMemorySize, SMEM_BYTES);

    pinn_kernel<<<NBLOCKS, NTHREADS, SMEM_BYTES>>>(
        x, t, W0, b0, W1, b1, W2, b2, W3, b3, (float*)d_out);
}